// round 2
// baseline (speedup 1.0000x reference)
#include <cuda_runtime.h>
#include <math.h>

#define NMAX 50000
#define EMAX 800000
#define DF   96

// Scratch (allocation-free: __device__ globals)
__device__ float g_h[NMAX * DF];       // projected features, 19.2 MB
__device__ int   g_cnt[NMAX];          // per-row degree
__device__ int   g_offs[NMAX + 1];     // CSR offsets
__device__ int   g_cur[NMAX];          // scatter cursors
__device__ int   g_sc[EMAX];           // sorted col per slot
__device__ float g_sw[EMAX];           // sorted weight per slot

// ---------------- zero counters ----------------
__global__ void zero_cnt_kernel(int n) {
    int i = blockIdx.x * blockDim.x + threadIdx.x;
    if (i < n) g_cnt[i] = 0;
}

// ---------------- dense projection: h = x @ W + b ----------------
// blockDim = (32, 8). Each block tile: 16 rows x 96 cols.
// Each thread: 2 rows x 3 cols register tile. W fully staged in smem.
__global__ void gemm_kernel(const float* __restrict__ x,
                            const float* __restrict__ W,
                            const float* __restrict__ b,
                            int N) {
    __shared__ float Ws[DF * DF];      // 36 KB
    __shared__ float xs[16][DF];

    const int tx  = threadIdx.x;       // 0..31
    const int ty  = threadIdx.y;       // 0..7
    const int tid = ty * 32 + tx;      // 0..255

    for (int i = tid; i < DF * DF; i += 256) Ws[i] = W[i];

    const float b0 = b[tx];
    const float b1 = b[tx + 32];
    const float b2 = b[tx + 64];

    for (int tile = blockIdx.x * 16; tile < N; tile += gridDim.x * 16) {
        __syncthreads();   // protect previous iteration's xs reads (and first Ws load)
        for (int i = tid; i < 16 * DF; i += 256) {
            int r = i / DF, c = i % DF;
            int gr = tile + r;
            xs[r][c] = (gr < N) ? x[gr * DF + c] : 0.0f;
        }
        __syncthreads();

        const int r0 = ty * 2, r1 = r0 + 1;
        float a00 = 0.f, a01 = 0.f, a02 = 0.f;
        float a10 = 0.f, a11 = 0.f, a12 = 0.f;
#pragma unroll
        for (int k = 0; k < DF; k++) {
            float w0 = Ws[k * DF + tx];
            float w1 = Ws[k * DF + tx + 32];
            float w2 = Ws[k * DF + tx + 64];
            float x0 = xs[r0][k];
            float x1 = xs[r1][k];
            a00 = fmaf(x0, w0, a00); a01 = fmaf(x0, w1, a01); a02 = fmaf(x0, w2, a02);
            a10 = fmaf(x1, w0, a10); a11 = fmaf(x1, w1, a11); a12 = fmaf(x1, w2, a12);
        }
        int gr0 = tile + r0, gr1 = tile + r1;
        if (gr0 < N) {
            float* hp = &g_h[(size_t)gr0 * DF];
            hp[tx] = a00 + b0; hp[tx + 32] = a01 + b1; hp[tx + 64] = a02 + b2;
        }
        if (gr1 < N) {
            float* hp = &g_h[(size_t)gr1 * DF];
            hp[tx] = a10 + b0; hp[tx + 32] = a11 + b1; hp[tx + 64] = a12 + b2;
        }
    }
}

// ---------------- degree histogram ----------------
__global__ void hist_kernel(const int* __restrict__ row, int E) {
    for (int i = blockIdx.x * blockDim.x + threadIdx.x; i < E;
         i += gridDim.x * blockDim.x) {
        atomicAdd(&g_cnt[row[i]], 1);
    }
}

// ---------------- exclusive prefix scan (single block, 1024 threads) -------
__global__ void scan_kernel(int n) {
    __shared__ int ts[1024];
    const int tid   = threadIdx.x;
    const int chunk = (n + 1023) >> 10;
    const int s0    = tid * chunk;
    const int s1    = min(s0 + chunk, n);

    int s = 0;
    for (int i = s0; i < s1; i++) s += g_cnt[i];
    ts[tid] = s;
    __syncthreads();

    // Hillis-Steele inclusive scan
    for (int d = 1; d < 1024; d <<= 1) {
        int v = 0;
        if (tid >= d) v = ts[tid - d];
        __syncthreads();
        if (tid >= d) ts[tid] += v;
        __syncthreads();
    }

    int base = (tid == 0) ? 0 : ts[tid - 1];
    for (int i = s0; i < s1; i++) {
        int c = g_cnt[i];
        g_offs[i] = base;
        g_cur[i]  = base;
        base += c;
    }
    if (s1 == n) g_offs[n] = base;   // total = E (threads past the end also write E)
}

// ---------------- bucket scatter into CSR slots ----------------
__global__ void scatter_kernel(const int* __restrict__ row,
                               const int* __restrict__ col,
                               const float* __restrict__ w, int E) {
    for (int i = blockIdx.x * blockDim.x + threadIdx.x; i < E;
         i += gridDim.x * blockDim.x) {
        int r = row[i];
        int p = atomicAdd(&g_cur[r], 1);
        g_sc[p] = col[i];
        g_sw[p] = w[i];
    }
}

// ---------------- warp-per-row gather + ELU ----------------
__global__ void gather_kernel(float* __restrict__ out, int N) {
    const int gwarp = (blockIdx.x * blockDim.x + threadIdx.x) >> 5;
    const int lane  = threadIdx.x & 31;
    if (gwarp >= N) return;

    const int s = g_offs[gwarp];
    const int e = g_offs[gwarp + 1];

    float a0 = 0.f, a1 = 0.f, a2 = 0.f;
    for (int i = s; i < e; i++) {
        const int   c  = g_sc[i];
        const float wv = g_sw[i];
        const float* hp = &g_h[(size_t)c * DF];
        a0 = fmaf(wv, hp[lane],      a0);
        a1 = fmaf(wv, hp[lane + 32], a1);
        a2 = fmaf(wv, hp[lane + 64], a2);
    }

    float* pre = out;
    float* act = out + (size_t)N * DF;
    const int o = gwarp * DF + lane;
    pre[o]      = a0;
    pre[o + 32] = a1;
    pre[o + 64] = a2;
    act[o]      = (a0 > 0.f) ? a0 : expm1f(a0);
    act[o + 32] = (a1 > 0.f) ? a1 : expm1f(a1);
    act[o + 64] = (a2 > 0.f) ? a2 : expm1f(a2);
}

// ---------------- launch ----------------
extern "C" void kernel_launch(void* const* d_in, const int* in_sizes, int n_in,
                              void* d_out, int out_size) {
    const float* x  = (const float*)d_in[0];
    const float* W  = (const float*)d_in[1];
    const float* b  = (const float*)d_in[2];
    const int*   ei = (const int*)d_in[3];
    const float* ew = (const float*)d_in[4];
    float* out = (float*)d_out;

    const int N = in_sizes[0] / DF;
    const int E = in_sizes[4];
    const int* row = ei;         // edge_index[0]
    const int* col = ei + E;     // edge_index[1]

    // 1) zero degree counters
    zero_cnt_kernel<<<(N + 255) / 256, 256>>>(N);

    // 2) dense projection (independent of 1/3/4/5 but serialized on stream; cheap)
    dim3 gblk(32, 8);
    gemm_kernel<<<1184, gblk>>>(x, W, b, N);

    // 3) degree histogram
    hist_kernel<<<592, 256>>>(row, E);

    // 4) exclusive scan -> CSR offsets + cursors
    scan_kernel<<<1, 1024>>>(N);

    // 5) bucket edges into CSR slots
    scatter_kernel<<<592, 256>>>(row, col, ew, E);

    // 6) warp-per-row weighted gather + ELU, writes (pre, elu) halves of d_out
    const int threads = 256;
    const int warps_needed = N;
    gather_kernel<<<(warps_needed * 32 + threads - 1) / threads, threads>>>(out, N);
}

// round 5
// speedup vs baseline: 1.6105x; 1.6105x over previous
#include <cuda_runtime.h>
#include <math.h>

#define NMAX 50000
#define EMAX 800000
#define DF   96
#define SCAN_B 1024

// Scratch (allocation-free: __device__ globals)
__device__ float g_h[NMAX * DF];       // projected features, 19.2 MB
__device__ int   g_cnt[NMAX];          // per-row degree
__device__ int   g_offs[NMAX + 1];     // CSR offsets
__device__ int   g_cur[NMAX];          // scatter cursors
__device__ int   g_part[64];           // per-block scan partials
__device__ int   g_sc[EMAX];           // sorted col per slot
__device__ float g_sw[EMAX];           // sorted weight per slot

// ---------------- zero counters ----------------
__global__ void zero_cnt_kernel(int n) {
    int i = blockIdx.x * blockDim.x + threadIdx.x;
    if (i < n) g_cnt[i] = 0;
}

// ---------------- dense projection: h = x @ W + b ----------------
__global__ void gemm_kernel(const float* __restrict__ x,
                            const float* __restrict__ W,
                            const float* __restrict__ b,
                            int N) {
    __shared__ float Ws[DF * DF];      // 36 KB
    __shared__ float xs[16][DF];

    const int tx  = threadIdx.x;       // 0..31
    const int ty  = threadIdx.y;       // 0..7
    const int tid = ty * 32 + tx;      // 0..255

    for (int i = tid; i < DF * DF; i += 256) Ws[i] = W[i];

    const float b0 = b[tx];
    const float b1 = b[tx + 32];
    const float b2 = b[tx + 64];

    for (int tile = blockIdx.x * 16; tile < N; tile += gridDim.x * 16) {
        __syncthreads();
        for (int i = tid; i < 16 * DF; i += 256) {
            int r = i / DF, c = i % DF;
            int gr = tile + r;
            xs[r][c] = (gr < N) ? x[gr * DF + c] : 0.0f;
        }
        __syncthreads();

        const int r0 = ty * 2, r1 = r0 + 1;
        float a00 = 0.f, a01 = 0.f, a02 = 0.f;
        float a10 = 0.f, a11 = 0.f, a12 = 0.f;
#pragma unroll
        for (int k = 0; k < DF; k++) {
            float w0 = Ws[k * DF + tx];
            float w1 = Ws[k * DF + tx + 32];
            float w2 = Ws[k * DF + tx + 64];
            float x0 = xs[r0][k];
            float x1 = xs[r1][k];
            a00 = fmaf(x0, w0, a00); a01 = fmaf(x0, w1, a01); a02 = fmaf(x0, w2, a02);
            a10 = fmaf(x1, w0, a10); a11 = fmaf(x1, w1, a11); a12 = fmaf(x1, w2, a12);
        }
        int gr0 = tile + r0, gr1 = tile + r1;
        if (gr0 < N) {
            float* hp = &g_h[(size_t)gr0 * DF];
            hp[tx] = a00 + b0; hp[tx + 32] = a01 + b1; hp[tx + 64] = a02 + b2;
        }
        if (gr1 < N) {
            float* hp = &g_h[(size_t)gr1 * DF];
            hp[tx] = a10 + b0; hp[tx + 32] = a11 + b1; hp[tx + 64] = a12 + b2;
        }
    }
}

// ---------------- degree histogram ----------------
__global__ void hist_kernel(const int* __restrict__ row, int E) {
    for (int i = blockIdx.x * blockDim.x + threadIdx.x; i < E;
         i += gridDim.x * blockDim.x) {
        atomicAdd(&g_cnt[row[i]], 1);
    }
}

// ---------------- multi-block exclusive scan, phase 1 ----------------
// Block-local exclusive scan of g_cnt into g_offs; block total -> g_part.
__global__ void scan1_kernel(int n) {
    __shared__ int warpsum[32];
    const int i    = blockIdx.x * SCAN_B + threadIdx.x;
    const int lane = threadIdx.x & 31;
    const int wid  = threadIdx.x >> 5;

    int v = (i < n) ? g_cnt[i] : 0;

    // warp inclusive scan
    int inc = v;
#pragma unroll
    for (int d = 1; d < 32; d <<= 1) {
        int t = __shfl_up_sync(0xFFFFFFFFu, inc, d);
        if (lane >= d) inc += t;
    }
    if (lane == 31) warpsum[wid] = inc;
    __syncthreads();

    if (wid == 0) {
        int ws = warpsum[lane];
#pragma unroll
        for (int d = 1; d < 32; d <<= 1) {
            int t = __shfl_up_sync(0xFFFFFFFFu, ws, d);
            if (lane >= d) ws += t;
        }
        warpsum[lane] = ws;
    }
    __syncthreads();

    const int base = (wid > 0) ? warpsum[wid - 1] : 0;
    if (i < n) g_offs[i] = base + inc - v;      // exclusive, block-local
    if (threadIdx.x == 0) g_part[blockIdx.x] = warpsum[31];  // block total
}

// ---------------- phase 2: exclusive scan of <=64 block partials ----------
__global__ void scan2_kernel(int nb) {
    __shared__ int s[64];
    const int t = threadIdx.x;          // blockDim = 64
    s[t] = (t < nb) ? g_part[t] : 0;
    __syncthreads();
#pragma unroll
    for (int d = 1; d < 64; d <<= 1) {
        int v = (t >= d) ? s[t - d] : 0;
        __syncthreads();
        s[t] += v;
        __syncthreads();
    }
    g_part[t] = (t == 0) ? 0 : s[t - 1];   // exclusive
}

// ---------------- phase 3: add block base, init cursors ----------------
__global__ void scan3_kernel(int n, int E) {
    const int i = blockIdx.x * SCAN_B + threadIdx.x;
    if (i < n) {
        int o = g_offs[i] + g_part[blockIdx.x];
        g_offs[i] = o;
        g_cur[i]  = o;
    }
    if (i == 0) g_offs[n] = E;
}

// ---------------- bucket scatter into CSR slots ----------------
__global__ void scatter_kernel(const int* __restrict__ row,
                               const int* __restrict__ col,
                               const float* __restrict__ w, int E) {
    for (int i = blockIdx.x * blockDim.x + threadIdx.x; i < E;
         i += gridDim.x * blockDim.x) {
        int r = row[i];
        int p = atomicAdd(&g_cur[r], 1);
        g_sc[p] = col[i];
        g_sw[p] = w[i];
    }
}

// ---------------- warp-per-row gather + ELU ----------------
__global__ void gather_kernel(float* __restrict__ out, int N) {
    const int gwarp = (blockIdx.x * blockDim.x + threadIdx.x) >> 5;
    const int lane  = threadIdx.x & 31;
    if (gwarp >= N) return;

    const int s = g_offs[gwarp];
    const int e = g_offs[gwarp + 1];

    float a0 = 0.f, a1 = 0.f, a2 = 0.f;
    int i = s;
    for (; i + 1 < e; i += 2) {      // x2 unroll -> 2 independent load chains
        const int   c0 = g_sc[i],     c1 = g_sc[i + 1];
        const float w0 = g_sw[i],     w1 = g_sw[i + 1];
        const float* h0 = &g_h[(size_t)c0 * DF];
        const float* h1 = &g_h[(size_t)c1 * DF];
        float p0 = h0[lane], p1 = h0[lane + 32], p2 = h0[lane + 64];
        float q0 = h1[lane], q1 = h1[lane + 32], q2 = h1[lane + 64];
        a0 = fmaf(w0, p0, a0); a1 = fmaf(w0, p1, a1); a2 = fmaf(w0, p2, a2);
        a0 = fmaf(w1, q0, a0); a1 = fmaf(w1, q1, a1); a2 = fmaf(w1, q2, a2);
    }
    if (i < e) {
        const int   c  = g_sc[i];
        const float wv = g_sw[i];
        const float* hp = &g_h[(size_t)c * DF];
        a0 = fmaf(wv, hp[lane],      a0);
        a1 = fmaf(wv, hp[lane + 32], a1);
        a2 = fmaf(wv, hp[lane + 64], a2);
    }

    float* pre = out;
    float* act = out + (size_t)N * DF;
    const int o = gwarp * DF + lane;
    pre[o]      = a0;
    pre[o + 32] = a1;
    pre[o + 64] = a2;
    act[o]      = (a0 > 0.f) ? a0 : expm1f(a0);
    act[o + 32] = (a1 > 0.f) ? a1 : expm1f(a1);
    act[o + 64] = (a2 > 0.f) ? a2 : expm1f(a2);
}

// ---------------- launch ----------------
extern "C" void kernel_launch(void* const* d_in, const int* in_sizes, int n_in,
                              void* d_out, int out_size) {
    const float* x  = (const float*)d_in[0];
    const float* W  = (const float*)d_in[1];
    const float* b  = (const float*)d_in[2];
    const int*   ei = (const int*)d_in[3];
    const float* ew = (const float*)d_in[4];
    float* out = (float*)d_out;

    const int N = in_sizes[0] / DF;
    const int E = in_sizes[4];
    const int* row = ei;         // edge_index[0]
    const int* col = ei + E;     // edge_index[1]

    const int nScanBlocks = (N + SCAN_B - 1) / SCAN_B;   // 49 for N=50000

    // 1) zero degree counters
    zero_cnt_kernel<<<(N + 255) / 256, 256>>>(N);

    // 2) dense projection
    dim3 gblk(32, 8);
    gemm_kernel<<<1184, gblk>>>(x, W, b, N);

    // 3) degree histogram
    hist_kernel<<<592, 256>>>(row, E);

    // 4) multi-block exclusive scan -> CSR offsets + cursors
    scan1_kernel<<<nScanBlocks, SCAN_B>>>(N);
    scan2_kernel<<<1, 64>>>(nScanBlocks);
    scan3_kernel<<<nScanBlocks, SCAN_B>>>(N, E);

    // 5) bucket edges into CSR slots
    scatter_kernel<<<592, 256>>>(row, col, ew, E);

    // 6) warp-per-row weighted gather + ELU
    const int threads = 256;
    gather_kernel<<<((size_t)N * 32 + threads - 1) / threads, threads>>>(out, N);
}

// round 6
// speedup vs baseline: 1.8539x; 1.1512x over previous
#include <cuda_runtime.h>
#include <math.h>

#define NMAX 50000
#define EMAX 800000
#define DF   96
#define SCAN_B 1024

// Scratch (allocation-free: __device__ globals)
__device__ float g_h[NMAX * DF];       // projected features, 19.2 MB
__device__ int   g_cnt[NMAX];          // per-row degree
__device__ int   g_offs[NMAX + 1];     // CSR offsets
__device__ int   g_cur[NMAX];          // scatter cursors
__device__ int   g_part[64];           // per-block scan partials
__device__ int2  g_e[EMAX];            // packed (col, weight-bits) per CSR slot

// ---------------- zero counters ----------------
__global__ void zero_cnt_kernel(int n) {
    int i = blockIdx.x * blockDim.x + threadIdx.x;
    if (i < n) g_cnt[i] = 0;
}

// ---------------- dense projection: h = x @ W + b ----------------
// blockDim = (32, 8). Block tile: 32 rows x 96 cols. Thread: 4 rows x 3 cols.
__global__ void gemm_kernel(const float* __restrict__ x,
                            const float* __restrict__ W,
                            const float* __restrict__ b,
                            int N) {
    __shared__ float Ws[DF * DF];      // 36 KB
    __shared__ float xs[32][DF];       // 12 KB

    const int tx  = threadIdx.x;       // 0..31
    const int ty  = threadIdx.y;       // 0..7
    const int tid = ty * 32 + tx;      // 0..255

    for (int i = tid; i < DF * DF; i += 256) Ws[i] = W[i];

    const float b0 = b[tx];
    const float b1 = b[tx + 32];
    const float b2 = b[tx + 64];

    const int tile = blockIdx.x * 32;
    if (tile >= N) return;

    for (int i = tid; i < 32 * DF; i += 256) {
        int r = i / DF, c = i % DF;
        int gr = tile + r;
        xs[r][c] = (gr < N) ? x[(size_t)gr * DF + c] : 0.0f;
    }
    __syncthreads();

    const int r0 = ty * 4;
    float a[4][3];
#pragma unroll
    for (int j = 0; j < 4; j++) { a[j][0] = 0.f; a[j][1] = 0.f; a[j][2] = 0.f; }

#pragma unroll 4
    for (int k = 0; k < DF; k++) {
        float w0 = Ws[k * DF + tx];
        float w1 = Ws[k * DF + tx + 32];
        float w2 = Ws[k * DF + tx + 64];
#pragma unroll
        for (int j = 0; j < 4; j++) {
            float xv = xs[r0 + j][k];
            a[j][0] = fmaf(xv, w0, a[j][0]);
            a[j][1] = fmaf(xv, w1, a[j][1]);
            a[j][2] = fmaf(xv, w2, a[j][2]);
        }
    }

#pragma unroll
    for (int j = 0; j < 4; j++) {
        int gr = tile + r0 + j;
        if (gr < N) {
            float* hp = &g_h[(size_t)gr * DF];
            hp[tx]      = a[j][0] + b0;
            hp[tx + 32] = a[j][1] + b1;
            hp[tx + 64] = a[j][2] + b2;
        }
    }
}

// ---------------- degree histogram ----------------
__global__ void hist_kernel(const int* __restrict__ row, int E) {
    for (int i = blockIdx.x * blockDim.x + threadIdx.x; i < E;
         i += gridDim.x * blockDim.x) {
        atomicAdd(&g_cnt[row[i]], 1);
    }
}

// ---------------- multi-block exclusive scan, phase 1 ----------------
__global__ void scan1_kernel(int n) {
    __shared__ int warpsum[32];
    const int i    = blockIdx.x * SCAN_B + threadIdx.x;
    const int lane = threadIdx.x & 31;
    const int wid  = threadIdx.x >> 5;

    int v = (i < n) ? g_cnt[i] : 0;

    int inc = v;
#pragma unroll
    for (int d = 1; d < 32; d <<= 1) {
        int t = __shfl_up_sync(0xFFFFFFFFu, inc, d);
        if (lane >= d) inc += t;
    }
    if (lane == 31) warpsum[wid] = inc;
    __syncthreads();

    if (wid == 0) {
        int ws = warpsum[lane];
#pragma unroll
        for (int d = 1; d < 32; d <<= 1) {
            int t = __shfl_up_sync(0xFFFFFFFFu, ws, d);
            if (lane >= d) ws += t;
        }
        warpsum[lane] = ws;
    }
    __syncthreads();

    const int base = (wid > 0) ? warpsum[wid - 1] : 0;
    if (i < n) g_offs[i] = base + inc - v;
    if (threadIdx.x == 0) g_part[blockIdx.x] = warpsum[31];
}

// ---------------- phase 2: exclusive scan of <=64 block partials ----------
__global__ void scan2_kernel(int nb) {
    __shared__ int s[64];
    const int t = threadIdx.x;
    s[t] = (t < nb) ? g_part[t] : 0;
    __syncthreads();
#pragma unroll
    for (int d = 1; d < 64; d <<= 1) {
        int v = (t >= d) ? s[t - d] : 0;
        __syncthreads();
        s[t] += v;
        __syncthreads();
    }
    g_part[t] = (t == 0) ? 0 : s[t - 1];
}

// ---------------- phase 3: add block base, init cursors ----------------
__global__ void scan3_kernel(int n, int E) {
    const int i = blockIdx.x * SCAN_B + threadIdx.x;
    if (i < n) {
        int o = g_offs[i] + g_part[blockIdx.x];
        g_offs[i] = o;
        g_cur[i]  = o;
    }
    if (i == 0) g_offs[n] = E;
}

// ---------------- bucket scatter into CSR slots (packed 8B payload) ------
__global__ void scatter_kernel(const int* __restrict__ row,
                               const int* __restrict__ col,
                               const float* __restrict__ w, int E) {
    for (int i = blockIdx.x * blockDim.x + threadIdx.x; i < E;
         i += gridDim.x * blockDim.x) {
        int r = row[i];
        int p = atomicAdd(&g_cur[r], 1);
        g_e[p] = make_int2(col[i], __float_as_int(w[i]));
    }
}

// ---------------- warp-per-row gather + ELU ----------------
__global__ void gather_kernel(float* __restrict__ out, int N) {
    const int gwarp = (blockIdx.x * blockDim.x + threadIdx.x) >> 5;
    const int lane  = threadIdx.x & 31;
    if (gwarp >= N) return;

    const int s = g_offs[gwarp];
    const int e = g_offs[gwarp + 1];

    float a0 = 0.f, a1 = 0.f, a2 = 0.f;
    int i = s;
    for (; i + 1 < e; i += 2) {      // x2 unroll -> 2 independent load chains
        const int2 e0 = g_e[i];
        const int2 e1 = g_e[i + 1];
        const float w0 = __int_as_float(e0.y);
        const float w1 = __int_as_float(e1.y);
        const float* h0 = &g_h[(size_t)e0.x * DF];
        const float* h1 = &g_h[(size_t)e1.x * DF];
        float p0 = h0[lane], p1 = h0[lane + 32], p2 = h0[lane + 64];
        float q0 = h1[lane], q1 = h1[lane + 32], q2 = h1[lane + 64];
        a0 = fmaf(w0, p0, a0); a1 = fmaf(w0, p1, a1); a2 = fmaf(w0, p2, a2);
        a0 = fmaf(w1, q0, a0); a1 = fmaf(w1, q1, a1); a2 = fmaf(w1, q2, a2);
    }
    if (i < e) {
        const int2 e0 = g_e[i];
        const float wv = __int_as_float(e0.y);
        const float* hp = &g_h[(size_t)e0.x * DF];
        a0 = fmaf(wv, hp[lane],      a0);
        a1 = fmaf(wv, hp[lane + 32], a1);
        a2 = fmaf(wv, hp[lane + 64], a2);
    }

    float* pre = out;
    float* act = out + (size_t)N * DF;
    const int o = gwarp * DF + lane;
    pre[o]      = a0;
    pre[o + 32] = a1;
    pre[o + 64] = a2;
    act[o]      = (a0 > 0.f) ? a0 : expm1f(a0);
    act[o + 32] = (a1 > 0.f) ? a1 : expm1f(a1);
    act[o + 64] = (a2 > 0.f) ? a2 : expm1f(a2);
}

// ---------------- launch ----------------
extern "C" void kernel_launch(void* const* d_in, const int* in_sizes, int n_in,
                              void* d_out, int out_size) {
    const float* x  = (const float*)d_in[0];
    const float* W  = (const float*)d_in[1];
    const float* b  = (const float*)d_in[2];
    const int*   ei = (const int*)d_in[3];
    const float* ew = (const float*)d_in[4];
    float* out = (float*)d_out;

    const int N = in_sizes[0] / DF;
    const int E = in_sizes[4];
    const int* row = ei;         // edge_index[0]
    const int* col = ei + E;     // edge_index[1]

    const int nScanBlocks = (N + SCAN_B - 1) / SCAN_B;   // 49 for N=50000

    // One-time side-stream + events. Created during the (uncaptured)
    // correctness call; the captured graph sees only launches and
    // record/wait dependency edges. No device memory is ever allocated here.
    static cudaStream_t s_side = nullptr;
    static cudaEvent_t  ev_fork = nullptr, ev_join = nullptr;
    if (s_side == nullptr) {
        cudaStreamCreateWithFlags(&s_side, cudaStreamNonBlocking);
        cudaEventCreateWithFlags(&ev_fork, cudaEventDisableTiming);
        cudaEventCreateWithFlags(&ev_join, cudaEventDisableTiming);
    }

    // Fork: GEMM runs on the side stream, concurrent with the edge chain.
    cudaEventRecord(ev_fork, 0);
    cudaStreamWaitEvent(s_side, ev_fork, 0);
    dim3 gblk(32, 8);
    gemm_kernel<<<(N + 31) / 32, gblk, 0, s_side>>>(x, W, b, N);
    cudaEventRecord(ev_join, s_side);

    // Edge chain on the main (captured) stream.
    zero_cnt_kernel<<<(N + 255) / 256, 256>>>(N);
    hist_kernel<<<592, 256>>>(row, E);
    scan1_kernel<<<nScanBlocks, SCAN_B>>>(N);
    scan2_kernel<<<1, 64>>>(nScanBlocks);
    scan3_kernel<<<nScanBlocks, SCAN_B>>>(N, E);
    scatter_kernel<<<592, 256>>>(row, col, ew, E);

    // Join: gather needs both g_h (GEMM) and the CSR (edge chain).
    cudaStreamWaitEvent(0, ev_join, 0);
    const int threads = 256;
    gather_kernel<<<((size_t)N * 32 + threads - 1) / threads, threads>>>(out, N);
}

// round 8
// speedup vs baseline: 1.8654x; 1.0062x over previous
#include <cuda_runtime.h>
#include <math.h>

#define NMAX 50000
#define EMAX 800000
#define DF   96
#define SCAN_B 1024
#define NSB  ((NMAX + SCAN_B - 1) / SCAN_B)   // 49 scan blocks

// Scratch (allocation-free: __device__ globals)
__device__ float g_h[NMAX * DF];       // projected features, 19.2 MB
__device__ int   g_cnt[NMAX];          // per-row degree
__device__ int   g_offs[NMAX + 1];     // CSR offsets
__device__ int   g_cur[NMAX];          // scatter cursors
__device__ unsigned long long g_desc[64];  // lookback descriptors
__device__ int2  g_e[EMAX];            // packed (col, weight-bits) per CSR slot

// ---------------- zero counters + lookback descriptors ----------------
__global__ void zero_kernel(int n) {
    int i = blockIdx.x * blockDim.x + threadIdx.x;
    if (i < n) g_cnt[i] = 0;
    if (i < 64) g_desc[i] = 0ULL;
}

// ---------------- dense projection: h = x @ W + b ----------------
// blockDim = (32, 8). Block tile: 32 rows x 96 cols. Thread: 4 rows x 3 cols.
__global__ void gemm_kernel(const float* __restrict__ x,
                            const float* __restrict__ W,
                            const float* __restrict__ b,
                            int N) {
    __shared__ float Ws[DF * DF];      // 36 KB
    __shared__ float xs[32][DF];       // 12 KB

    const int tx  = threadIdx.x;       // 0..31
    const int ty  = threadIdx.y;       // 0..7
    const int tid = ty * 32 + tx;      // 0..255

    for (int i = tid; i < DF * DF; i += 256) Ws[i] = W[i];

    const float b0 = b[tx];
    const float b1 = b[tx + 32];
    const float b2 = b[tx + 64];

    const int tile = blockIdx.x * 32;
    if (tile >= N) return;

    for (int i = tid; i < 32 * DF; i += 256) {
        int r = i / DF, c = i % DF;
        int gr = tile + r;
        xs[r][c] = (gr < N) ? x[(size_t)gr * DF + c] : 0.0f;
    }
    __syncthreads();

    const int r0 = ty * 4;
    float a[4][3];
#pragma unroll
    for (int j = 0; j < 4; j++) { a[j][0] = 0.f; a[j][1] = 0.f; a[j][2] = 0.f; }

#pragma unroll 4
    for (int k = 0; k < DF; k++) {
        float w0 = Ws[k * DF + tx];
        float w1 = Ws[k * DF + tx + 32];
        float w2 = Ws[k * DF + tx + 64];
#pragma unroll
        for (int j = 0; j < 4; j++) {
            float xv = xs[r0 + j][k];
            a[j][0] = fmaf(xv, w0, a[j][0]);
            a[j][1] = fmaf(xv, w1, a[j][1]);
            a[j][2] = fmaf(xv, w2, a[j][2]);
        }
    }

#pragma unroll
    for (int j = 0; j < 4; j++) {
        int gr = tile + r0 + j;
        if (gr < N) {
            float* hp = &g_h[(size_t)gr * DF];
            hp[tx]      = a[j][0] + b0;
            hp[tx + 32] = a[j][1] + b1;
            hp[tx + 64] = a[j][2] + b2;
        }
    }
}

// ---------------- degree histogram (int4 vectorized) ----------------
__global__ void hist_kernel(const int* __restrict__ row, int E) {
    const int E4 = E >> 2;
    const int4* r4 = (const int4*)row;
    for (int i = blockIdx.x * blockDim.x + threadIdx.x; i < E4;
         i += gridDim.x * blockDim.x) {
        int4 v = r4[i];
        atomicAdd(&g_cnt[v.x], 1);
        atomicAdd(&g_cnt[v.y], 1);
        atomicAdd(&g_cnt[v.z], 1);
        atomicAdd(&g_cnt[v.w], 1);
    }
    // remainder
    for (int i = (E4 << 2) + blockIdx.x * blockDim.x + threadIdx.x; i < E;
         i += gridDim.x * blockDim.x) {
        atomicAdd(&g_cnt[row[i]], 1);
    }
}

// ---------------- single-pass decoupled-lookback exclusive scan ----------
// Descriptor: bits[62:64) = state (0 invalid, 1 aggregate, 2 prefix),
//             bits[0:32)  = value.
__global__ void scan_lookback_kernel(int n, int E) {
    __shared__ int warpsum[32];
    __shared__ int s_prefix;

    const int bid  = blockIdx.x;
    const int i    = bid * SCAN_B + threadIdx.x;
    const int lane = threadIdx.x & 31;
    const int wid  = threadIdx.x >> 5;

    int v = (i < n) ? g_cnt[i] : 0;

    // block-local inclusive scan (shuffle + warp partials)
    int inc = v;
#pragma unroll
    for (int d = 1; d < 32; d <<= 1) {
        int t = __shfl_up_sync(0xFFFFFFFFu, inc, d);
        if (lane >= d) inc += t;
    }
    if (lane == 31) warpsum[wid] = inc;
    __syncthreads();
    if (wid == 0) {
        int ws = warpsum[lane];
#pragma unroll
        for (int d = 1; d < 32; d <<= 1) {
            int t = __shfl_up_sync(0xFFFFFFFFu, ws, d);
            if (lane >= d) ws += t;
        }
        warpsum[lane] = ws;
    }
    __syncthreads();

    const int wbase     = (wid > 0) ? warpsum[wid - 1] : 0;
    const int local_exc = wbase + inc - v;          // block-local exclusive
    const int block_agg = warpsum[31];              // block total

    // publish + lookback (thread 0)
    if (threadIdx.x == 0) {
        if (bid == 0) {
            __threadfence();
            atomicExch(&g_desc[0], (2ULL << 62) | (unsigned)block_agg);
            s_prefix = 0;
        } else {
            atomicExch(&g_desc[bid], (1ULL << 62) | (unsigned)block_agg);
            int running = 0;
            int j = bid - 1;
            while (j >= 0) {
                unsigned long long d;
                do {
                    d = atomicAdd(&g_desc[j], 0ULL);   // volatile-read
                } while ((d >> 62) == 0ULL);
                running += (int)(d & 0xFFFFFFFFULL);
                if ((d >> 62) == 2ULL) break;          // inclusive prefix found
                j--;
            }
            __threadfence();
            atomicExch(&g_desc[bid],
                       (2ULL << 62) | (unsigned)(running + block_agg));
            s_prefix = running;
        }
    }
    __syncthreads();

    const int base = s_prefix;
    if (i < n) {
        int o = base + local_exc;
        g_offs[i] = o;
        g_cur[i]  = o;
    }
    if (i == 0) g_offs[n] = E;
}

// ---------------- bucket scatter into CSR slots (vectorized reads) -------
__global__ void scatter_kernel(const int* __restrict__ row,
                               const int* __restrict__ col,
                               const float* __restrict__ w, int E) {
    const int E4 = E >> 2;
    const int4*   r4 = (const int4*)row;
    const int4*   c4 = (const int4*)col;
    const float4* w4 = (const float4*)w;
    for (int i = blockIdx.x * blockDim.x + threadIdx.x; i < E4;
         i += gridDim.x * blockDim.x) {
        int4   r = r4[i];
        int4   c = c4[i];
        float4 wv = w4[i];
        int p;
        p = atomicAdd(&g_cur[r.x], 1); g_e[p] = make_int2(c.x, __float_as_int(wv.x));
        p = atomicAdd(&g_cur[r.y], 1); g_e[p] = make_int2(c.y, __float_as_int(wv.y));
        p = atomicAdd(&g_cur[r.z], 1); g_e[p] = make_int2(c.z, __float_as_int(wv.z));
        p = atomicAdd(&g_cur[r.w], 1); g_e[p] = make_int2(c.w, __float_as_int(wv.w));
    }
    for (int i = (E4 << 2) + blockIdx.x * blockDim.x + threadIdx.x; i < E;
         i += gridDim.x * blockDim.x) {
        int p = atomicAdd(&g_cur[row[i]], 1);
        g_e[p] = make_int2(col[i], __float_as_int(w[i]));
    }
}

// ---------------- warp-per-row gather + ELU (x4 unroll) ----------------
__global__ void gather_kernel(float* __restrict__ out, int N) {
    const int gwarp = (blockIdx.x * blockDim.x + threadIdx.x) >> 5;
    const int lane  = threadIdx.x & 31;
    if (gwarp >= N) return;

    const int s = g_offs[gwarp];
    const int e = g_offs[gwarp + 1];

    float a0 = 0.f, a1 = 0.f, a2 = 0.f;
    int i = s;
    for (; i + 3 < e; i += 4) {
        const int2 e0 = g_e[i];
        const int2 e1 = g_e[i + 1];
        const int2 e2 = g_e[i + 2];
        const int2 e3 = g_e[i + 3];
        const float* h0 = &g_h[(size_t)e0.x * DF];
        const float* h1 = &g_h[(size_t)e1.x * DF];
        const float* h2 = &g_h[(size_t)e2.x * DF];
        const float* h3 = &g_h[(size_t)e3.x * DF];
        float p00 = h0[lane], p01 = h0[lane + 32], p02 = h0[lane + 64];
        float p10 = h1[lane], p11 = h1[lane + 32], p12 = h1[lane + 64];
        float p20 = h2[lane], p21 = h2[lane + 32], p22 = h2[lane + 64];
        float p30 = h3[lane], p31 = h3[lane + 32], p32 = h3[lane + 64];
        const float w0 = __int_as_float(e0.y);
        const float w1 = __int_as_float(e1.y);
        const float w2 = __int_as_float(e2.y);
        const float w3 = __int_as_float(e3.y);
        a0 = fmaf(w0, p00, a0); a1 = fmaf(w0, p01, a1); a2 = fmaf(w0, p02, a2);
        a0 = fmaf(w1, p10, a0); a1 = fmaf(w1, p11, a1); a2 = fmaf(w1, p12, a2);
        a0 = fmaf(w2, p20, a0); a1 = fmaf(w2, p21, a1); a2 = fmaf(w2, p22, a2);
        a0 = fmaf(w3, p30, a0); a1 = fmaf(w3, p31, a1); a2 = fmaf(w3, p32, a2);
    }
    for (; i < e; i++) {
        const int2 e0 = g_e[i];
        const float wv = __int_as_float(e0.y);
        const float* hp = &g_h[(size_t)e0.x * DF];
        a0 = fmaf(wv, hp[lane],      a0);
        a1 = fmaf(wv, hp[lane + 32], a1);
        a2 = fmaf(wv, hp[lane + 64], a2);
    }

    float* pre = out;
    float* act = out + (size_t)N * DF;
    const int o = gwarp * DF + lane;
    pre[o]      = a0;
    pre[o + 32] = a1;
    pre[o + 64] = a2;
    act[o]      = (a0 > 0.f) ? a0 : expm1f(a0);
    act[o + 32] = (a1 > 0.f) ? a1 : expm1f(a1);
    act[o + 64] = (a2 > 0.f) ? a2 : expm1f(a2);
}

// ---------------- launch ----------------
extern "C" void kernel_launch(void* const* d_in, const int* in_sizes, int n_in,
                              void* d_out, int out_size) {
    const float* x  = (const float*)d_in[0];
    const float* W  = (const float*)d_in[1];
    const float* b  = (const float*)d_in[2];
    const int*   ei = (const int*)d_in[3];
    const float* ew = (const float*)d_in[4];
    float* out = (float*)d_out;

    const int N = in_sizes[0] / DF;
    const int E = in_sizes[4];
    const int* row = ei;         // edge_index[0]
    const int* col = ei + E;     // edge_index[1]

    const int nScanBlocks = (N + SCAN_B - 1) / SCAN_B;   // 49 for N=50000

    // One-time side-stream + events (created during the uncaptured
    // correctness call; no device memory allocated anywhere).
    static cudaStream_t s_side = nullptr;
    static cudaEvent_t  ev_fork = nullptr, ev_join = nullptr;
    if (s_side == nullptr) {
        cudaStreamCreateWithFlags(&s_side, cudaStreamNonBlocking);
        cudaEventCreateWithFlags(&ev_fork, cudaEventDisableTiming);
        cudaEventCreateWithFlags(&ev_join, cudaEventDisableTiming);
    }

    // Fork: GEMM on side stream, concurrent with edge chain.
    cudaEventRecord(ev_fork, 0);
    cudaStreamWaitEvent(s_side, ev_fork, 0);
    dim3 gblk(32, 8);
    gemm_kernel<<<(N + 31) / 32, gblk, 0, s_side>>>(x, W, b, N);
    cudaEventRecord(ev_join, s_side);

    // Edge chain on main (captured) stream.
    zero_kernel<<<(N + 255) / 256, 256>>>(N);
    hist_kernel<<<296, 256>>>(row, E);
    scan_lookback_kernel<<<nScanBlocks, SCAN_B>>>(N, E);
    scatter_kernel<<<296, 256>>>(row, col, ew, E);

    // Join: gather needs both g_h (GEMM) and the CSR (edge chain).
    cudaStreamWaitEvent(0, ev_join, 0);
    const int threads = 256;
    gather_kernel<<<((size_t)N * 32 + threads - 1) / threads, threads>>>(out, N);
}

// round 9
// speedup vs baseline: 1.9446x; 1.0425x over previous
#include <cuda_runtime.h>
#include <math.h>

#define NMAX 50000
#define EMAX 800000
#define DF   96
// scan: 256 threads x 4 elems = 1024 elems per block
#define SCAN_T 256
#define SCAN_E 1024

// Scratch (allocation-free: __device__ globals). 16B-aligned for int4 access.
__device__ __align__(16) float g_h[NMAX * DF];     // projected features
__device__ __align__(16) int   g_cnt[NMAX];        // per-row degree (zero at entry)
__device__ __align__(16) int   g_offs[NMAX + 4];   // CSR offsets (padded)
__device__ __align__(16) int   g_cur[NMAX];        // scatter cursors
__device__ int   g_part[64];                       // per-block scan partials
__device__ __align__(16) int2  g_e[EMAX];          // packed (col, w-bits) per slot

// ---------------- dense projection: h = x @ W + b ----------------
// blockDim = (32, 8). Block tile: 32 rows x 96 cols. Thread: 4 rows x 3 cols.
__global__ void gemm_kernel(const float* __restrict__ x,
                            const float* __restrict__ W,
                            const float* __restrict__ b,
                            int N) {
    __shared__ float Ws[DF * DF];      // 36 KB
    __shared__ float xs[32][DF];       // 12 KB

    const int tx  = threadIdx.x;
    const int ty  = threadIdx.y;
    const int tid = ty * 32 + tx;

    for (int i = tid; i < DF * DF; i += 256) Ws[i] = W[i];

    const float b0 = b[tx];
    const float b1 = b[tx + 32];
    const float b2 = b[tx + 64];

    const int tile = blockIdx.x * 32;
    if (tile >= N) return;

    for (int i = tid; i < 32 * DF; i += 256) {
        int r = i / DF, c = i % DF;
        int gr = tile + r;
        xs[r][c] = (gr < N) ? x[(size_t)gr * DF + c] : 0.0f;
    }
    __syncthreads();

    const int r0 = ty * 4;
    float a[4][3];
#pragma unroll
    for (int j = 0; j < 4; j++) { a[j][0] = 0.f; a[j][1] = 0.f; a[j][2] = 0.f; }

#pragma unroll 4
    for (int k = 0; k < DF; k++) {
        float w0 = Ws[k * DF + tx];
        float w1 = Ws[k * DF + tx + 32];
        float w2 = Ws[k * DF + tx + 64];
#pragma unroll
        for (int j = 0; j < 4; j++) {
            float xv = xs[r0 + j][k];
            a[j][0] = fmaf(xv, w0, a[j][0]);
            a[j][1] = fmaf(xv, w1, a[j][1]);
            a[j][2] = fmaf(xv, w2, a[j][2]);
        }
    }

#pragma unroll
    for (int j = 0; j < 4; j++) {
        int gr = tile + r0 + j;
        if (gr < N) {
            float* hp = &g_h[(size_t)gr * DF];
            hp[tx]      = a[j][0] + b0;
            hp[tx + 32] = a[j][1] + b1;
            hp[tx + 64] = a[j][2] + b2;
        }
    }
}

// ---------------- degree histogram (int4 vectorized) ----------------
// g_cnt is zero on entry (module-load init / restored by scan3 each call).
__global__ void hist_kernel(const int* __restrict__ row, int E) {
    const int E4 = E >> 2;
    const int4* r4 = (const int4*)row;
    for (int i = blockIdx.x * blockDim.x + threadIdx.x; i < E4;
         i += gridDim.x * blockDim.x) {
        int4 v = r4[i];
        atomicAdd(&g_cnt[v.x], 1);
        atomicAdd(&g_cnt[v.y], 1);
        atomicAdd(&g_cnt[v.z], 1);
        atomicAdd(&g_cnt[v.w], 1);
    }
    for (int i = (E4 << 2) + blockIdx.x * blockDim.x + threadIdx.x; i < E;
         i += gridDim.x * blockDim.x) {
        atomicAdd(&g_cnt[row[i]], 1);
    }
}

// ---------------- scan phase 1: block-local exclusive scan (int4) --------
__global__ void scan1_kernel(int n) {
    __shared__ int warpsum[8];
    const int tid  = threadIdx.x;            // 0..255
    const int lane = tid & 31;
    const int wid  = tid >> 5;
    const int e0   = blockIdx.x * SCAN_E + tid * 4;

    int4 v;
    v.x = (e0     < n) ? g_cnt[e0]     : 0;
    v.y = (e0 + 1 < n) ? g_cnt[e0 + 1] : 0;
    v.z = (e0 + 2 < n) ? g_cnt[e0 + 2] : 0;
    v.w = (e0 + 3 < n) ? g_cnt[e0 + 3] : 0;
    const int tsum = v.x + v.y + v.z + v.w;

    // warp inclusive scan of per-thread sums
    int inc = tsum;
#pragma unroll
    for (int d = 1; d < 32; d <<= 1) {
        int t = __shfl_up_sync(0xFFFFFFFFu, inc, d);
        if (lane >= d) inc += t;
    }
    if (lane == 31) warpsum[wid] = inc;
    __syncthreads();
    if (tid < 8) {
        int ws = warpsum[tid];
#pragma unroll
        for (int d = 1; d < 8; d <<= 1) {
            int t = __shfl_up_sync(0xFFu, ws, d);
            if ((tid & 7) >= d) ws += t;
        }
        warpsum[tid] = ws;
    }
    __syncthreads();

    const int base = ((wid > 0) ? warpsum[wid - 1] : 0) + inc - tsum;

    if (e0 + 3 < n) {
        int4 o;
        o.x = base;
        o.y = base + v.x;
        o.z = o.y + v.y;
        o.w = o.z + v.z;
        *(int4*)&g_offs[e0] = o;
    } else {
        int run = base;
        if (e0     < n) { g_offs[e0]     = run; run += v.x; }
        if (e0 + 1 < n) { g_offs[e0 + 1] = run; run += v.y; }
        if (e0 + 2 < n) { g_offs[e0 + 2] = run; run += v.z; }
        if (e0 + 3 < n) { g_offs[e0 + 3] = run; }
    }
    if (tid == SCAN_T - 1) g_part[blockIdx.x] = warpsum[7];
}

// ---------------- scan phase 2: exclusive scan of <=64 block partials ----
__global__ void scan2_kernel(int nb) {
    const int t = threadIdx.x;          // blockDim = 64
    int v = (t < nb) ? g_part[t] : 0;
    int inc = v;
    const unsigned full = 0xFFFFFFFFu;
#pragma unroll
    for (int d = 1; d < 32; d <<= 1) {
        int u = __shfl_up_sync(full, inc, d);
        if ((t & 31) >= d) inc += u;
    }
    __shared__ int w0sum;
    if (t == 31) w0sum = inc;
    __syncthreads();
    int base = (t >= 32) ? w0sum : 0;
    g_part[t] = base + inc - v;          // exclusive
}

// ---------------- scan phase 3: add base, init cursors, re-zero cnt ------
__global__ void scan3_kernel(int n, int E) {
    const int tid = threadIdx.x;
    const int e0  = blockIdx.x * SCAN_E + tid * 4;
    const int base = g_part[blockIdx.x];
    const int4 z = make_int4(0, 0, 0, 0);

    if (e0 + 3 < n) {
        int4 o = *(const int4*)&g_offs[e0];
        o.x += base; o.y += base; o.z += base; o.w += base;
        *(int4*)&g_offs[e0] = o;
        *(int4*)&g_cur[e0]  = o;
        *(int4*)&g_cnt[e0]  = z;         // restore invariant for next call
    } else {
#pragma unroll
        for (int j = 0; j < 4; j++) {
            int i = e0 + j;
            if (i < n) {
                int o = g_offs[i] + base;
                g_offs[i] = o;
                g_cur[i]  = o;
                g_cnt[i]  = 0;
            }
        }
    }
    if (e0 == 0) g_offs[n] = E;
}

// ---------------- bucket scatter into CSR slots (vectorized reads) -------
__global__ void scatter_kernel(const int* __restrict__ row,
                               const int* __restrict__ col,
                               const float* __restrict__ w, int E) {
    const int E4 = E >> 2;
    const int4*   r4 = (const int4*)row;
    const int4*   c4 = (const int4*)col;
    const float4* w4 = (const float4*)w;
    for (int i = blockIdx.x * blockDim.x + threadIdx.x; i < E4;
         i += gridDim.x * blockDim.x) {
        int4   r = r4[i];
        int4   c = c4[i];
        float4 wv = w4[i];
        int p;
        p = atomicAdd(&g_cur[r.x], 1); g_e[p] = make_int2(c.x, __float_as_int(wv.x));
        p = atomicAdd(&g_cur[r.y], 1); g_e[p] = make_int2(c.y, __float_as_int(wv.y));
        p = atomicAdd(&g_cur[r.z], 1); g_e[p] = make_int2(c.z, __float_as_int(wv.z));
        p = atomicAdd(&g_cur[r.w], 1); g_e[p] = make_int2(c.w, __float_as_int(wv.w));
    }
    for (int i = (E4 << 2) + blockIdx.x * blockDim.x + threadIdx.x; i < E;
         i += gridDim.x * blockDim.x) {
        int p = atomicAdd(&g_cur[row[i]], 1);
        g_e[p] = make_int2(col[i], __float_as_int(w[i]));
    }
}

// ---------------- warp-per-row gather + ELU (x4 unroll) ----------------
__global__ void gather_kernel(float* __restrict__ out, int N) {
    const int gwarp = (blockIdx.x * blockDim.x + threadIdx.x) >> 5;
    const int lane  = threadIdx.x & 31;
    if (gwarp >= N) return;

    const int s = g_offs[gwarp];
    const int e = g_offs[gwarp + 1];

    float a0 = 0.f, a1 = 0.f, a2 = 0.f;
    int i = s;
    for (; i + 3 < e; i += 4) {
        const int2 e0 = g_e[i];
        const int2 e1 = g_e[i + 1];
        const int2 e2 = g_e[i + 2];
        const int2 e3 = g_e[i + 3];
        const float* h0 = &g_h[(size_t)e0.x * DF];
        const float* h1 = &g_h[(size_t)e1.x * DF];
        const float* h2 = &g_h[(size_t)e2.x * DF];
        const float* h3 = &g_h[(size_t)e3.x * DF];
        float p00 = h0[lane], p01 = h0[lane + 32], p02 = h0[lane + 64];
        float p10 = h1[lane], p11 = h1[lane + 32], p12 = h1[lane + 64];
        float p20 = h2[lane], p21 = h2[lane + 32], p22 = h2[lane + 64];
        float p30 = h3[lane], p31 = h3[lane + 32], p32 = h3[lane + 64];
        const float w0 = __int_as_float(e0.y);
        const float w1 = __int_as_float(e1.y);
        const float w2 = __int_as_float(e2.y);
        const float w3 = __int_as_float(e3.y);
        a0 = fmaf(w0, p00, a0); a1 = fmaf(w0, p01, a1); a2 = fmaf(w0, p02, a2);
        a0 = fmaf(w1, p10, a0); a1 = fmaf(w1, p11, a1); a2 = fmaf(w1, p12, a2);
        a0 = fmaf(w2, p20, a0); a1 = fmaf(w2, p21, a1); a2 = fmaf(w2, p22, a2);
        a0 = fmaf(w3, p30, a0); a1 = fmaf(w3, p31, a1); a2 = fmaf(w3, p32, a2);
    }
    for (; i < e; i++) {
        const int2 e0 = g_e[i];
        const float wv = __int_as_float(e0.y);
        const float* hp = &g_h[(size_t)e0.x * DF];
        a0 = fmaf(wv, hp[lane],      a0);
        a1 = fmaf(wv, hp[lane + 32], a1);
        a2 = fmaf(wv, hp[lane + 64], a2);
    }

    float* pre = out;
    float* act = out + (size_t)N * DF;
    const int o = gwarp * DF + lane;
    pre[o]      = a0;
    pre[o + 32] = a1;
    pre[o + 64] = a2;
    act[o]      = (a0 > 0.f) ? a0 : expm1f(a0);
    act[o + 32] = (a1 > 0.f) ? a1 : expm1f(a1);
    act[o + 64] = (a2 > 0.f) ? a2 : expm1f(a2);
}

// ---------------- launch ----------------
extern "C" void kernel_launch(void* const* d_in, const int* in_sizes, int n_in,
                              void* d_out, int out_size) {
    const float* x  = (const float*)d_in[0];
    const float* W  = (const float*)d_in[1];
    const float* b  = (const float*)d_in[2];
    const int*   ei = (const int*)d_in[3];
    const float* ew = (const float*)d_in[4];
    float* out = (float*)d_out;

    const int N = in_sizes[0] / DF;
    const int E = in_sizes[4];
    const int* row = ei;         // edge_index[0]
    const int* col = ei + E;     // edge_index[1]

    const int nScanBlocks = (N + SCAN_E - 1) / SCAN_E;   // 49 for N=50000

    // One-time side-stream + events (created during the uncaptured
    // correctness call; no device memory allocated anywhere).
    static cudaStream_t s_side = nullptr;
    static cudaEvent_t  ev_fork = nullptr, ev_join = nullptr;
    if (s_side == nullptr) {
        cudaStreamCreateWithFlags(&s_side, cudaStreamNonBlocking);
        cudaEventCreateWithFlags(&ev_fork, cudaEventDisableTiming);
        cudaEventCreateWithFlags(&ev_join, cudaEventDisableTiming);
    }

    // Fork: GEMM on side stream, concurrent with edge chain.
    cudaEventRecord(ev_fork, 0);
    cudaStreamWaitEvent(s_side, ev_fork, 0);
    dim3 gblk(32, 8);
    gemm_kernel<<<(N + 31) / 32, gblk, 0, s_side>>>(x, W, b, N);
    cudaEventRecord(ev_join, s_side);

    // Edge chain on main (captured) stream. g_cnt is zero on entry
    // (module-load init; scan3 restores it every call).
    hist_kernel<<<592, 256>>>(row, E);
    scan1_kernel<<<nScanBlocks, SCAN_T>>>(N);
    scan2_kernel<<<1, 64>>>(nScanBlocks);
    scan3_kernel<<<nScanBlocks, SCAN_T>>>(N, E);
    scatter_kernel<<<592, 256>>>(row, col, ew, E);

    // Join: gather needs both g_h (GEMM) and the CSR (edge chain).
    cudaStreamWaitEvent(0, ev_join, 0);
    const int threads = 256;
    gather_kernel<<<((size_t)N * 32 + threads - 1) / threads, threads>>>(out, N);
}